// round 1
// baseline (speedup 1.0000x reference)
#include <cuda_runtime.h>

// ---------------------------------------------------------------------------
// ClusterLoss: out = mean((X-dec)^2) + ALPHA * soft_kmeans_loss(enc, K=64)
// Shapes: X/dec 65536x512 fp32, enc 65536x64 fp32, K=64, 10 iters, BETA=1.
// Only the last iteration's loss is returned; the 10th C-update is dead.
// ---------------------------------------------------------------------------

#define NROWS   65536
#define DLAT    64
#define KC      64
#define NDATA   33554432      // 65536*512
#define ALPHA   0.001f
#define EPSV    1e-8f
#define RPB     256           // rows per block in kmeans kernels
#define RSTRIDE 65            // padded smem row stride (conflict-free scalar access)

// Device-global scratch (no allocations allowed)
__device__ float g_C[KC * DLAT];
__device__ float g_RtE[KC * DLAT];
__device__ float g_sumR[KC];
__device__ float g_dec;
__device__ float g_loss;

// ---------------------------------------------------------------------------
__global__ void init_kernel(const float* __restrict__ enc) {
    int t = threadIdx.x;
    for (int i = t; i < KC * DLAT; i += blockDim.x) {
        g_C[i]   = enc[i];      // C = enc[:K]
        g_RtE[i] = 0.f;
    }
    if (t < KC) g_sumR[t] = 0.f;
    if (t == 0) { g_dec = 0.f; g_loss = 0.f; }
}

// ---------------------------------------------------------------------------
// Decoder loss: grid-stride float4 stream over X and dec, hierarchical reduce.
__global__ void decoder_kernel(const float4* __restrict__ X,
                               const float4* __restrict__ Dc, int n4) {
    float s = 0.f;
    for (int i = blockIdx.x * blockDim.x + threadIdx.x; i < n4;
         i += gridDim.x * blockDim.x) {
        float4 x = __ldg(X + i);
        float4 d = __ldg(Dc + i);
        float a = x.x - d.x, b = x.y - d.y, c = x.z - d.z, w = x.w - d.w;
        s = fmaf(a, a, fmaf(b, b, fmaf(c, c, fmaf(w, w, s))));
    }
    #pragma unroll
    for (int o = 16; o; o >>= 1) s += __shfl_down_sync(0xffffffffu, s, o);
    __shared__ float ws[8];
    int lane = threadIdx.x & 31, wid = threadIdx.x >> 5;
    if (lane == 0) ws[wid] = s;
    __syncthreads();
    if (wid == 0) {
        s = (lane < 8) ? ws[lane] : 0.f;
        #pragma unroll
        for (int o = 4; o; o >>= 1) s += __shfl_down_sync(0xffffffffu, s, o);
        if (lane == 0) atomicAdd(&g_dec, s);
    }
}

// ---------------------------------------------------------------------------
// One k-means assignment iteration, fused with the C-update partial GEMM.
// Block = 256 threads = 256 rows. Stage 1: d2 -> softmax r (row in regs,
// C in smem). Stage 2: block-local 64x64 R^T @ E via stride-65 smem tiles,
// atomically reduced into g_RtE / g_sumR.
extern __shared__ float s_dyn[];
__global__ void __launch_bounds__(256, 1)
assign_kernel(const float* __restrict__ enc) {
    float* sC  = s_dyn;                    // 4096
    float* sC2 = sC + KC * DLAT;           // 64
    float* sR  = sC2 + KC;                 // 256*65
    float* sE  = sR + RPB * RSTRIDE;       // 256*65
    int t = threadIdx.x;

    for (int i = t; i < KC * DLAT; i += 256) sC[i] = g_C[i];
    __syncthreads();
    if (t < KC) {
        float s = 0.f;
        #pragma unroll
        for (int d = 0; d < DLAT; d++) s = fmaf(sC[t * DLAT + d], sC[t * DLAT + d], s);
        sC2[t] = s;
    }

    // Load this thread's row into registers (and stage into sE for stage 2).
    float e[DLAT];
    int row = blockIdx.x * RPB + t;
    const float4* ep = (const float4*)(enc + (size_t)row * DLAT);
    #pragma unroll
    for (int i = 0; i < DLAT / 4; i++) {
        float4 v = __ldg(ep + i);
        e[4 * i + 0] = v.x; e[4 * i + 1] = v.y;
        e[4 * i + 2] = v.z; e[4 * i + 3] = v.w;
        sE[t * RSTRIDE + 4 * i + 0] = v.x;
        sE[t * RSTRIDE + 4 * i + 1] = v.y;
        sE[t * RSTRIDE + 4 * i + 2] = v.z;
        sE[t * RSTRIDE + 4 * i + 3] = v.w;
    }
    float x2 = 0.f;
    #pragma unroll
    for (int d = 0; d < DLAT; d++) x2 = fmaf(e[d], e[d], x2);
    __syncthreads();  // sC2 + sE ready

    // d2 against all 64 centroids
    float d2[KC];
    float mind = 3.402823e38f;
    #pragma unroll
    for (int k = 0; k < KC; k++) {
        float acc = 0.f;
        #pragma unroll
        for (int d = 0; d < DLAT; d++) acc = fmaf(e[d], sC[k * DLAT + d], acc);
        float v = fmaxf(x2 + sC2[k] - 2.f * acc, 0.f);
        d2[k] = v;
        mind = fminf(mind, v);
    }
    // Stable softmax of -d2 (reuse d2 regs for exp values)
    float se = 0.f;
    #pragma unroll
    for (int k = 0; k < KC; k++) { float ev = __expf(mind - d2[k]); d2[k] = ev; se += ev; }
    float inv = 1.f / se;
    #pragma unroll
    for (int k = 0; k < KC; k++) sR[t * RSTRIDE + k] = d2[k] * inv;
    __syncthreads();

    // Stage 2: RtE[k0..k0+3][d0..d0+3] partial over 256 rows
    int k0 = (t & 15) * 4;
    int d0 = (t >> 4) * 4;
    float acc[4][4];
    #pragma unroll
    for (int a = 0; a < 4; a++)
        #pragma unroll
        for (int b = 0; b < 4; b++) acc[a][b] = 0.f;
    for (int r = 0; r < RPB; r++) {
        float rv[4], ev2[4];
        #pragma unroll
        for (int j = 0; j < 4; j++) rv[j]  = sR[r * RSTRIDE + k0 + j];
        #pragma unroll
        for (int j = 0; j < 4; j++) ev2[j] = sE[r * RSTRIDE + d0 + j];
        #pragma unroll
        for (int a = 0; a < 4; a++)
            #pragma unroll
            for (int b = 0; b < 4; b++) acc[a][b] = fmaf(rv[a], ev2[b], acc[a][b]);
    }
    #pragma unroll
    for (int a = 0; a < 4; a++)
        #pragma unroll
        for (int b = 0; b < 4; b++)
            atomicAdd(&g_RtE[(k0 + a) * DLAT + d0 + b], acc[a][b]);

    if (t < KC) {
        float s = 0.f;
        for (int r = 0; r < RPB; r++) s += sR[r * RSTRIDE + t];
        atomicAdd(&g_sumR[t], s);
    }
}

// ---------------------------------------------------------------------------
__global__ void update_kernel() {
    int t = threadIdx.x;
    for (int i = t; i < KC * DLAT; i += blockDim.x) {
        int k = i >> 6;
        g_C[i] = g_RtE[i] / (g_sumR[k] + EPSV);
    }
    __syncthreads();
    for (int i = t; i < KC * DLAT; i += blockDim.x) g_RtE[i] = 0.f;
    if (t < KC) g_sumR[t] = 0.f;
}

// ---------------------------------------------------------------------------
// Final iteration: compute loss = mean_i sum_k r*d2 only (no C update needed).
__global__ void __launch_bounds__(256, 1)
loss_kernel(const float* __restrict__ enc) {
    __shared__ float sC[KC * DLAT];
    __shared__ float sC2[KC];
    __shared__ float ws[8];
    int t = threadIdx.x;
    for (int i = t; i < KC * DLAT; i += 256) sC[i] = g_C[i];
    __syncthreads();
    if (t < KC) {
        float s = 0.f;
        #pragma unroll
        for (int d = 0; d < DLAT; d++) s = fmaf(sC[t * DLAT + d], sC[t * DLAT + d], s);
        sC2[t] = s;
    }
    float e[DLAT];
    int row = blockIdx.x * RPB + t;
    const float4* ep = (const float4*)(enc + (size_t)row * DLAT);
    #pragma unroll
    for (int i = 0; i < DLAT / 4; i++) {
        float4 v = __ldg(ep + i);
        e[4 * i + 0] = v.x; e[4 * i + 1] = v.y;
        e[4 * i + 2] = v.z; e[4 * i + 3] = v.w;
    }
    float x2 = 0.f;
    #pragma unroll
    for (int d = 0; d < DLAT; d++) x2 = fmaf(e[d], e[d], x2);
    __syncthreads();

    float d2[KC];
    float mind = 3.402823e38f;
    #pragma unroll
    for (int k = 0; k < KC; k++) {
        float acc = 0.f;
        #pragma unroll
        for (int d = 0; d < DLAT; d++) acc = fmaf(e[d], sC[k * DLAT + d], acc);
        float v = fmaxf(x2 + sC2[k] - 2.f * acc, 0.f);
        d2[k] = v;
        mind = fminf(mind, v);
    }
    float se = 0.f, sed = 0.f;
    #pragma unroll
    for (int k = 0; k < KC; k++) {
        float ev = __expf(mind - d2[k]);
        se += ev;
        sed = fmaf(ev, d2[k], sed);
    }
    float rl = sed / se;   // per-row sum_k r*d2

    #pragma unroll
    for (int o = 16; o; o >>= 1) rl += __shfl_down_sync(0xffffffffu, rl, o);
    int lane = t & 31, wid = t >> 5;
    if (lane == 0) ws[wid] = rl;
    __syncthreads();
    if (wid == 0) {
        rl = (lane < 8) ? ws[lane] : 0.f;
        #pragma unroll
        for (int o = 4; o; o >>= 1) rl += __shfl_down_sync(0xffffffffu, rl, o);
        if (lane == 0) atomicAdd(&g_loss, rl);
    }
}

// ---------------------------------------------------------------------------
__global__ void finalize_kernel(float* out) {
    out[0] = g_dec * (1.f / (float)NDATA) + ALPHA * (g_loss * (1.f / (float)NROWS));
}

// ---------------------------------------------------------------------------
extern "C" void kernel_launch(void* const* d_in, const int* in_sizes, int n_in,
                              void* d_out, int out_size) {
    // metadata order: X, encoding, decoding, K — pick encoding robustly by size.
    const float* X   = (const float*)d_in[0];
    const float* enc = (const float*)d_in[1];
    const float* dec = (const float*)d_in[2];
    if (n_in >= 3) {
        if (in_sizes[0] == NROWS * DLAT) { enc = (const float*)d_in[0]; X = (const float*)d_in[1]; dec = (const float*)d_in[2]; }
        else if (in_sizes[2] == NROWS * DLAT) { enc = (const float*)d_in[2]; dec = (const float*)d_in[1]; }
    }
    float* out = (float*)d_out;

    const int SMEM_BYTES = (KC * DLAT + KC + 2 * RPB * RSTRIDE) * (int)sizeof(float); // 149760
    cudaFuncSetAttribute(assign_kernel, cudaFuncAttributeMaxDynamicSharedMemorySize, SMEM_BYTES);

    init_kernel<<<1, 256>>>(enc);
    decoder_kernel<<<2048, 256>>>((const float4*)X, (const float4*)dec, NDATA / 4);
    for (int it = 0; it < 9; it++) {
        assign_kernel<<<NROWS / RPB, 256, SMEM_BYTES>>>(enc);
        update_kernel<<<1, 256>>>();
    }
    loss_kernel<<<NROWS / RPB, 256>>>(enc);
    finalize_kernel<<<1, 1>>>(out);
}

// round 2
// speedup vs baseline: 1.0897x; 1.0897x over previous
#include <cuda_runtime.h>
#include <cuda_bf16.h>

// ---------------------------------------------------------------------------
// ClusterLoss: out = mean((X-dec)^2) + ALPHA * soft_kmeans_loss(enc, K=64)
// enc 65536x64 fp32 (L2-resident), X/dec 65536x512 fp32, 10 iters, BETA=1.
// Iteration kernel: one wave (grid = #SMs), ~432 rows/block, fused
// assignment + softmax (FMA-pipe exp) + block-local R^T@E partial GEMM +
// last-block C-update epilogue (no separate update kernel).
// ---------------------------------------------------------------------------

#define NROWS   65536
#define DLAT    64
#define KC      64
#define NDATA   33554432      // 65536*512
#define ALPHA   0.001f
#define EPSV    1e-8f
#define RST     68            // row stride: floats for sR, bf16 elems for sE
#define BIGF    3.402823e38f

__device__ float    g_C[KC * DLAT];
__device__ float    g_RtE[KC * DLAT];
__device__ float    g_sumR[KC];
__device__ float    g_dec;
__device__ float    g_loss;
__device__ unsigned g_ticket;

// ---------------------------------------------------------------------------
__global__ void init_kernel(const float* __restrict__ enc) {
    int t = threadIdx.x;
    for (int i = t; i < KC * DLAT; i += blockDim.x) {
        g_C[i]   = enc[i];     // C = enc[:K]
        g_RtE[i] = 0.f;
    }
    if (t < KC) g_sumR[t] = 0.f;
    if (t == 0) { g_dec = 0.f; g_loss = 0.f; g_ticket = 0u; }
}

// ---------------------------------------------------------------------------
// Decoder loss: HBM-bound float4 stream.
__global__ void decoder_kernel(const float4* __restrict__ X,
                               const float4* __restrict__ Dc, int n4) {
    float s = 0.f;
    for (int i = blockIdx.x * blockDim.x + threadIdx.x; i < n4;
         i += gridDim.x * blockDim.x) {
        float4 x = __ldg(X + i);
        float4 d = __ldg(Dc + i);
        float a = x.x - d.x, b = x.y - d.y, c = x.z - d.z, w = x.w - d.w;
        s = fmaf(a, a, fmaf(b, b, fmaf(c, c, fmaf(w, w, s))));
    }
    #pragma unroll
    for (int o = 16; o; o >>= 1) s += __shfl_down_sync(0xffffffffu, s, o);
    __shared__ float ws[8];
    int lane = threadIdx.x & 31, wid = threadIdx.x >> 5;
    if (lane == 0) ws[wid] = s;
    __syncthreads();
    if (wid == 0) {
        s = (lane < 8) ? ws[lane] : 0.f;
        #pragma unroll
        for (int o = 4; o; o >>= 1) s += __shfl_down_sync(0xffffffffu, s, o);
        if (lane == 0) atomicAdd(&g_dec, s);
    }
}

// ---------------------------------------------------------------------------
// exp(x), x <= 0, on the FMA/ALU pipes only (no MUFU).
// exp(x)=2^y, y=x*log2e; round via magic constant, degree-4 poly on [-.5,.5].
__device__ __forceinline__ float fexp(float x) {
    float y = x * 1.44269504f;
    y = fmaxf(y, -126.0f);
    float t = y + 12582912.0f;           // round-to-nearest-int in mantissa
    float n = t - 12582912.0f;           // float-valued integer part
    float f = y - n;                     // fractional part in [-0.5, 0.5]
    float p = 0.00961812911f;
    p = fmaf(p, f, 0.0555041087f);
    p = fmaf(p, f, 0.240226507f);
    p = fmaf(p, f, 0.693147181f);
    p = fmaf(p, f, 1.0f);
    // 2^n from the magic-number bits: low 9 bits of t's encoding hold n mod 512
    float s = __int_as_float((__float_as_int(t) << 23) + 0x3F800000);
    return s * p;
}

// ---------------------------------------------------------------------------
// One k-means iteration (is_loss=0: assignment + C-update accumulate + epilogue;
// is_loss=1: final loss only). Grid = #SMs, single wave.
extern __shared__ float s_dyn[];
__global__ void __launch_bounds__(256, 1)
iter_kernel(const float* __restrict__ enc, int is_loss) {
    float* sC  = s_dyn;                   // 4096 floats
    float* sC2 = s_dyn + 4096;            // 64
    float* sR  = s_dyn + 4160;            // rpb*RST floats (16B-aligned rows)
    __shared__ float ws[8];
    __shared__ unsigned s_last;

    int t = threadIdx.x;
    int g = gridDim.x;
    int rpb = (NROWS + g - 1) / g;
    __nv_bfloat16* sE = (__nv_bfloat16*)(sR + rpb * RST);
    int row0 = blockIdx.x * rpb;
    int rows = NROWS - row0; if (rows > rpb) rows = rpb;

    for (int i = t; i < KC * DLAT; i += 256) sC[i] = g_C[i];
    __syncthreads();
    if (t < KC) {
        float s = 0.f;
        #pragma unroll
        for (int d = 0; d < DLAT; d++) s = fmaf(sC[t * DLAT + d], sC[t * DLAT + d], s);
        sC2[t] = s;
    }
    __syncthreads();

    float blk_loss = 0.f;
    for (int r = t; r < rows; r += 256) {
        const float4* ep = (const float4*)(enc + (size_t)(row0 + r) * DLAT);
        float e[DLAT];
        #pragma unroll
        for (int j = 0; j < DLAT / 4; j++) {
            float4 v = __ldg(ep + j);
            e[4*j+0] = v.x; e[4*j+1] = v.y; e[4*j+2] = v.z; e[4*j+3] = v.w;
        }
        if (!is_loss) {
            __nv_bfloat162* se2 = (__nv_bfloat162*)(sE + r * RST);
            #pragma unroll
            for (int j = 0; j < DLAT / 2; j++)
                se2[j] = __floats2bfloat162_rn(e[2*j], e[2*j+1]);
        }
        float x2 = 0.f;
        #pragma unroll
        for (int d = 0; d < DLAT; d++) x2 = fmaf(e[d], e[d], x2);

        float d2v[KC];
        float mind = BIGF;
        #pragma unroll
        for (int k = 0; k < KC; k++) {
            const float4* c4 = (const float4*)(sC + k * DLAT);
            float a0 = 0.f, a1 = 0.f, a2 = 0.f, a3 = 0.f;
            #pragma unroll
            for (int j = 0; j < DLAT / 4; j++) {
                float4 cv = c4[j];
                a0 = fmaf(e[4*j+0], cv.x, a0);
                a1 = fmaf(e[4*j+1], cv.y, a1);
                a2 = fmaf(e[4*j+2], cv.z, a2);
                a3 = fmaf(e[4*j+3], cv.w, a3);
            }
            float dot = (a0 + a1) + (a2 + a3);
            float v = fmaxf(x2 + sC2[k] - 2.f * dot, 0.f);
            d2v[k] = v;
            mind = fminf(mind, v);
        }
        float se = 0.f, sed = 0.f;
        #pragma unroll
        for (int k = 0; k < KC; k++) {
            float ev = fexp(mind - d2v[k]);
            se  += ev;
            sed  = fmaf(ev, d2v[k], sed);
            d2v[k] = ev;
        }
        if (is_loss) {
            blk_loss += sed / se;
        } else {
            float inv = 1.f / se;
            #pragma unroll
            for (int k = 0; k < KC; k++) sR[r * RST + k] = d2v[k] * inv;
        }
    }

    if (is_loss) {
        #pragma unroll
        for (int o = 16; o; o >>= 1) blk_loss += __shfl_down_sync(0xffffffffu, blk_loss, o);
        int lane = t & 31, wid = t >> 5;
        if (lane == 0) ws[wid] = blk_loss;
        __syncthreads();
        if (wid == 0) {
            blk_loss = (lane < 8) ? ws[lane] : 0.f;
            #pragma unroll
            for (int o = 4; o; o >>= 1) blk_loss += __shfl_down_sync(0xffffffffu, blk_loss, o);
            if (lane == 0) atomicAdd(&g_loss, blk_loss);
        }
        return;
    }

    __syncthreads();   // sR / sE complete

    // Stage 2: block-local 64x64 partial of R^T @ E, 4x4 register tile/thread.
    {
        int k0 = (t & 15) << 2;
        int d0 = (t >> 4) << 2;
        float acc[4][4];
        #pragma unroll
        for (int a = 0; a < 4; a++)
            #pragma unroll
            for (int b = 0; b < 4; b++) acc[a][b] = 0.f;
        #pragma unroll 4
        for (int r = 0; r < rows; r++) {
            float4 rv = *(const float4*)(sR + r * RST + k0);
            const __nv_bfloat162* ev = (const __nv_bfloat162*)(sE + r * RST);
            float2 eA = __bfloat1622float2(ev[(d0 >> 1) + 0]);
            float2 eB = __bfloat1622float2(ev[(d0 >> 1) + 1]);
            float rr[4] = {rv.x, rv.y, rv.z, rv.w};
            float ee[4] = {eA.x, eA.y, eB.x, eB.y};
            #pragma unroll
            for (int a = 0; a < 4; a++)
                #pragma unroll
                for (int b = 0; b < 4; b++)
                    acc[a][b] = fmaf(rr[a], ee[b], acc[a][b]);
        }
        #pragma unroll
        for (int a = 0; a < 4; a++)
            #pragma unroll
            for (int b = 0; b < 4; b++)
                atomicAdd(&g_RtE[(k0 + a) * DLAT + d0 + b], acc[a][b]);
    }
    if (t < KC) {
        float s = 0.f;
        for (int r = 0; r < rows; r++) s += sR[r * RST + t];
        atomicAdd(&g_sumR[t], s);
    }

    // Last-arriving block performs the C update (replaces update_kernel).
    __threadfence();
    __syncthreads();
    if (t == 0)
        s_last = (atomicAdd(&g_ticket, 1u) == (unsigned)(g - 1)) ? 1u : 0u;
    __syncthreads();
    if (s_last) {
        __threadfence();
        for (int i = t; i < KC * DLAT; i += 256)
            g_C[i] = g_RtE[i] / (g_sumR[i >> 6] + EPSV);
        __syncthreads();
        for (int i = t; i < KC * DLAT; i += 256) g_RtE[i] = 0.f;
        if (t < KC) g_sumR[t] = 0.f;
        if (t == 0) g_ticket = 0u;
    }
}

// ---------------------------------------------------------------------------
__global__ void finalize_kernel(float* out) {
    out[0] = g_dec * (1.f / (float)NDATA) + ALPHA * (g_loss * (1.f / (float)NROWS));
}

// ---------------------------------------------------------------------------
extern "C" void kernel_launch(void* const* d_in, const int* in_sizes, int n_in,
                              void* d_out, int out_size) {
    const float* X   = (const float*)d_in[0];
    const float* enc = (const float*)d_in[1];
    const float* dec = (const float*)d_in[2];
    if (n_in >= 3) {
        if (in_sizes[0] == NROWS * DLAT)      { enc = (const float*)d_in[0]; X = (const float*)d_in[1]; dec = (const float*)d_in[2]; }
        else if (in_sizes[2] == NROWS * DLAT) { enc = (const float*)d_in[2]; dec = (const float*)d_in[1]; }
    }
    float* out = (float*)d_out;

    int sm = 148;
    cudaDeviceGetAttribute(&sm, cudaDevAttrMultiProcessorCount, 0);
    int g   = sm;
    int rpb = (NROWS + g - 1) / g;
    size_t smem = (size_t)(4160 + rpb * RST) * 4 + (size_t)rpb * RST * 2;
    cudaFuncSetAttribute(iter_kernel, cudaFuncAttributeMaxDynamicSharedMemorySize, (int)smem);

    init_kernel<<<1, 256>>>(enc);
    decoder_kernel<<<2048, 256>>>((const float4*)X, (const float4*)dec, NDATA / 4);
    for (int it = 0; it < 10; it++)
        iter_kernel<<<g, 256, smem>>>(enc, it == 9 ? 1 : 0);
    finalize_kernel<<<1, 1>>>(out);
}

// round 3
// speedup vs baseline: 1.8442x; 1.6924x over previous
#include <cuda_runtime.h>
#include <cuda_bf16.h>
#include <cstdint>

// ---------------------------------------------------------------------------
// ClusterLoss via tf32 mma.sync tensor cores.
// out = mean((X-dec)^2) + ALPHA * soft_kmeans_loss(enc, K=64), 10 iters.
// Per iteration: GEMM1 d2-dots (E @ C^T), softmax in fragment layout,
// GEMM2 (R^T @ [E|1]) with ones-column producing sumR, last-block C update.
// ---------------------------------------------------------------------------

#define NROWS   65536
#define DLAT    64
#define KC      64
#define NDATA   33554432
#define ALPHA   0.001f
#define EPSV    1e-8f
#define BIGF    3.402823e38f

#define SE_ST   76      // sE row stride (floats): 256 x 76, cols 0..63 data, 64 ones
#define SC_ST   68      // sC row stride
#define SRT_ST  260     // sRT row stride (64 clusters x 256 rows)

__device__ float    g_C[KC * DLAT];
__device__ float    g_RtE[KC * 72];      // col 64 = sumR
__device__ float    g_dec;
__device__ float    g_loss;
__device__ unsigned g_ticket;

// ---------------------------------------------------------------------------
__global__ void init_kernel(const float* __restrict__ enc) {
    int t = threadIdx.x;
    for (int i = t; i < KC * DLAT; i += blockDim.x) g_C[i] = enc[i];
    for (int i = t; i < KC * 72;   i += blockDim.x) g_RtE[i] = 0.f;
    if (t == 0) { g_dec = 0.f; g_loss = 0.f; g_ticket = 0u; }
}

// ---------------------------------------------------------------------------
__global__ void decoder_kernel(const float4* __restrict__ X,
                               const float4* __restrict__ Dc, int n4) {
    float s = 0.f;
    for (int i = blockIdx.x * blockDim.x + threadIdx.x; i < n4;
         i += gridDim.x * blockDim.x) {
        float4 x = __ldg(X + i);
        float4 d = __ldg(Dc + i);
        float a = x.x - d.x, b = x.y - d.y, c = x.z - d.z, w = x.w - d.w;
        s = fmaf(a, a, fmaf(b, b, fmaf(c, c, fmaf(w, w, s))));
    }
    #pragma unroll
    for (int o = 16; o; o >>= 1) s += __shfl_down_sync(0xffffffffu, s, o);
    __shared__ float ws[8];
    int lane = threadIdx.x & 31, wid = threadIdx.x >> 5;
    if (lane == 0) ws[wid] = s;
    __syncthreads();
    if (wid == 0) {
        s = (lane < 8) ? ws[lane] : 0.f;
        #pragma unroll
        for (int o = 4; o; o >>= 1) s += __shfl_down_sync(0xffffffffu, s, o);
        if (lane == 0) atomicAdd(&g_dec, s);
    }
}

// ---------------------------------------------------------------------------
__device__ __forceinline__ uint32_t f2tf(float f) {
    uint32_t u;
    asm("cvt.rna.tf32.f32 %0, %1;" : "=r"(u) : "f"(f));
    return u;
}

__device__ __forceinline__ void mma_tf32(float& d0, float& d1, float& d2, float& d3,
                                         uint32_t a0, uint32_t a1, uint32_t a2, uint32_t a3,
                                         uint32_t b0, uint32_t b1) {
    asm volatile(
        "mma.sync.aligned.m16n8k8.row.col.f32.tf32.tf32.f32 "
        "{%0,%1,%2,%3}, {%4,%5,%6,%7}, {%8,%9}, {%0,%1,%2,%3};"
        : "+f"(d0), "+f"(d1), "+f"(d2), "+f"(d3)
        : "r"(a0), "r"(a1), "r"(a2), "r"(a3), "r"(b0), "r"(b1));
}

// exp(x), x<=0, FMA-pipe only.
__device__ __forceinline__ float fexp(float x) {
    float y = x * 1.44269504f;
    y = fmaxf(y, -126.0f);
    float t = y + 12582912.0f;
    float n = t - 12582912.0f;
    float f = y - n;
    float p = 0.00961812911f;
    p = fmaf(p, f, 0.0555041087f);
    p = fmaf(p, f, 0.240226507f);
    p = fmaf(p, f, 0.693147181f);
    p = fmaf(p, f, 1.0f);
    float s = __int_as_float((__float_as_int(t) << 23) + 0x3F800000);
    return s * p;
}

// ---------------------------------------------------------------------------
// One iteration. Grid = 128 CTAs x 2 tiles of 256 rows. 256 threads (8 warps).
extern __shared__ float s_dyn[];
__global__ void __launch_bounds__(256, 1)
iter_kernel(const float* __restrict__ enc, int is_loss) {
    float* sC  = s_dyn;                       // 64*68
    float* sC2 = sC + KC * SC_ST;             // 64
    float* sX2 = sC2 + KC;                    // 256
    float* sE  = sX2 + 256;                   // 256*76
    float* sRT = sE + 256 * SE_ST;            // 64*260
    uint32_t* uC  = (uint32_t*)sC;
    uint32_t* uE  = (uint32_t*)sE;
    uint32_t* uRT = (uint32_t*)sRT;
    __shared__ float ws[8];
    __shared__ unsigned s_last;

    int t = threadIdx.x, lane = t & 31, warp = t >> 5;
    int lg = lane >> 2, lt = lane & 3;        // groupID, threadID-in-group

    // C -> smem (tf32), c2
    for (int i = t; i < KC * DLAT; i += 256) {
        int k = i >> 6, d = i & 63;
        uC[k * SC_ST + d] = f2tf(g_C[i]);
    }
    __syncthreads();
    if (t < KC) {
        float s = 0.f;
        #pragma unroll
        for (int d = 0; d < DLAT; d++) { float c = sC[t * SC_ST + d]; s = fmaf(c, c, s); }
        sC2[t] = s;
    }

    // GEMM2 accumulators persist across both tiles.
    int mt2 = warp & 3;                          // cluster m-tile (16 rows)
    int ntbase = (warp < 4) ? 0 : 5;
    int ntcnt  = (warp < 4) ? 5 : 4;             // n-tiles of [E|1] (9 total)
    float acc2[5][4];
    #pragma unroll
    for (int j = 0; j < 5; j++)
        #pragma unroll
        for (int c = 0; c < 4; c++) acc2[j][c] = 0.f;

    float blk_loss = 0.f;
    int m0 = warp * 32;

    for (int tile = 0; tile < 2; tile++) {
        __syncthreads();                         // protect sE/sRT reuse
        int row0 = (blockIdx.x * 2 + tile) * 256;

        // Load this tile's 256 E rows (thread t owns row t), tf32 in smem.
        {
            const float4* ep = (const float4*)(enc + (size_t)(row0 + t) * DLAT);
            float x2 = 0.f;
            #pragma unroll
            for (int j = 0; j < 16; j++) {
                float4 v = __ldg(ep + j);
                uint32_t u0 = f2tf(v.x), u1 = f2tf(v.y), u2 = f2tf(v.z), u3 = f2tf(v.w);
                uE[t * SE_ST + 4 * j + 0] = u0;
                uE[t * SE_ST + 4 * j + 1] = u1;
                uE[t * SE_ST + 4 * j + 2] = u2;
                uE[t * SE_ST + 4 * j + 3] = u3;
                float f0 = __uint_as_float(u0), f1 = __uint_as_float(u1);
                float f2 = __uint_as_float(u2), f3 = __uint_as_float(u3);
                x2 = fmaf(f0, f0, fmaf(f1, f1, fmaf(f2, f2, fmaf(f3, f3, x2))));
            }
            uE[t * SE_ST + 64] = f2tf(1.0f);     // ones column -> sumR
            #pragma unroll
            for (int j = 65; j < SE_ST; j++) uE[t * SE_ST + j] = 0u;
            sX2[t] = x2;
        }
        __syncthreads();

        // ---- GEMM1: dot = E_tile @ C^T (m=32/warp, n=64, k=64) ----
        float acc[2][8][4];
        #pragma unroll
        for (int mt = 0; mt < 2; mt++)
            #pragma unroll
            for (int nt = 0; nt < 8; nt++)
                #pragma unroll
                for (int c = 0; c < 4; c++) acc[mt][nt][c] = 0.f;

        #pragma unroll
        for (int kt = 0; kt < 8; kt++) {
            int k0 = kt * 8;
            uint32_t a[2][4];
            #pragma unroll
            for (int mt = 0; mt < 2; mt++) {
                int r = m0 + mt * 16 + lg;
                a[mt][0] = uE[r * SE_ST + k0 + lt];
                a[mt][1] = uE[(r + 8) * SE_ST + k0 + lt];
                a[mt][2] = uE[r * SE_ST + k0 + lt + 4];
                a[mt][3] = uE[(r + 8) * SE_ST + k0 + lt + 4];
            }
            #pragma unroll
            for (int nt = 0; nt < 8; nt++) {
                uint32_t b0 = uC[(nt * 8 + lg) * SC_ST + k0 + lt];
                uint32_t b1 = uC[(nt * 8 + lg) * SC_ST + k0 + lt + 4];
                mma_tf32(acc[0][nt][0], acc[0][nt][1], acc[0][nt][2], acc[0][nt][3],
                         a[0][0], a[0][1], a[0][2], a[0][3], b0, b1);
                mma_tf32(acc[1][nt][0], acc[1][nt][1], acc[1][nt][2], acc[1][nt][3],
                         a[1][0], a[1][1], a[1][2], a[1][3], b0, b1);
            }
        }

        // ---- softmax epilogue in fragment layout ----
        #pragma unroll
        for (int mt = 0; mt < 2; mt++) {
            #pragma unroll
            for (int h = 0; h < 2; h++) {
                int rloc = m0 + mt * 16 + h * 8 + lg;
                float x2v = sX2[rloc];
                float vals[16];
                #pragma unroll
                for (int nt = 0; nt < 8; nt++) {
                    #pragma unroll
                    for (int c = 0; c < 2; c++) {
                        int col = nt * 8 + lt * 2 + c;
                        float dot = acc[mt][nt][h * 2 + c];
                        vals[nt * 2 + c] = fmaxf(x2v + sC2[col] - 2.f * dot, 0.f);
                    }
                }
                float mn = vals[0];
                #pragma unroll
                for (int j = 1; j < 16; j++) mn = fminf(mn, vals[j]);
                mn = fminf(mn, __shfl_xor_sync(0xffffffffu, mn, 1));
                mn = fminf(mn, __shfl_xor_sync(0xffffffffu, mn, 2));
                float se = 0.f, sed = 0.f;
                #pragma unroll
                for (int j = 0; j < 16; j++) {
                    float ev = fexp(mn - vals[j]);
                    se += ev;
                    sed = fmaf(ev, vals[j], sed);
                    vals[j] = ev;
                }
                se  += __shfl_xor_sync(0xffffffffu, se, 1);
                se  += __shfl_xor_sync(0xffffffffu, se, 2);
                if (is_loss) {
                    sed += __shfl_xor_sync(0xffffffffu, sed, 1);
                    sed += __shfl_xor_sync(0xffffffffu, sed, 2);
                    if (lt == 0) blk_loss += sed / se;
                } else {
                    float inv = 1.f / se;
                    #pragma unroll
                    for (int nt = 0; nt < 8; nt++) {
                        #pragma unroll
                        for (int c = 0; c < 2; c++) {
                            int col = nt * 8 + lt * 2 + c;
                            uRT[col * SRT_ST + rloc] = f2tf(vals[nt * 2 + c] * inv);
                        }
                    }
                }
            }
        }
        if (is_loss) continue;
        __syncthreads();                         // sRT ready

        // ---- GEMM2: RtE += R^T (64x256) @ [E|1] (256x72) ----
        #pragma unroll 4
        for (int kt = 0; kt < 32; kt++) {
            int k0 = kt * 8;
            int ar = mt2 * 16 + lg;
            uint32_t a0 = uRT[ar * SRT_ST + k0 + lt];
            uint32_t a1 = uRT[(ar + 8) * SRT_ST + k0 + lt];
            uint32_t a2 = uRT[ar * SRT_ST + k0 + lt + 4];
            uint32_t a3 = uRT[(ar + 8) * SRT_ST + k0 + lt + 4];
            #pragma unroll
            for (int j = 0; j < 5; j++) {
                if (j < ntcnt) {
                    int n0 = (ntbase + j) * 8;
                    uint32_t b0 = uE[(k0 + lt) * SE_ST + n0 + lg];
                    uint32_t b1 = uE[(k0 + lt + 4) * SE_ST + n0 + lg];
                    mma_tf32(acc2[j][0], acc2[j][1], acc2[j][2], acc2[j][3],
                             a0, a1, a2, a3, b0, b1);
                }
            }
        }
    }

    if (is_loss) {
        #pragma unroll
        for (int o = 16; o; o >>= 1) blk_loss += __shfl_down_sync(0xffffffffu, blk_loss, o);
        if (lane == 0) ws[warp] = blk_loss;
        __syncthreads();
        if (warp == 0) {
            blk_loss = (lane < 8) ? ws[lane] : 0.f;
            #pragma unroll
            for (int o = 4; o; o >>= 1) blk_loss += __shfl_down_sync(0xffffffffu, blk_loss, o);
            if (lane == 0) atomicAdd(&g_loss, blk_loss);
        }
        return;
    }

    // Atomically reduce GEMM2 partials into g_RtE.
    #pragma unroll
    for (int j = 0; j < 5; j++) {
        if (j < ntcnt) {
            int n0 = (ntbase + j) * 8;
            int m  = mt2 * 16 + lg;
            int c0 = n0 + lt * 2;
            atomicAdd(&g_RtE[m * 72 + c0],           acc2[j][0]);
            atomicAdd(&g_RtE[m * 72 + c0 + 1],       acc2[j][1]);
            atomicAdd(&g_RtE[(m + 8) * 72 + c0],     acc2[j][2]);
            atomicAdd(&g_RtE[(m + 8) * 72 + c0 + 1], acc2[j][3]);
        }
    }

    // Last block updates C.
    __threadfence();
    __syncthreads();
    if (t == 0)
        s_last = (atomicAdd(&g_ticket, 1u) == (unsigned)(gridDim.x - 1)) ? 1u : 0u;
    __syncthreads();
    if (s_last) {
        __threadfence();
        for (int i = t; i < KC * DLAT; i += 256) {
            int k = i >> 6, d = i & 63;
            g_C[i] = g_RtE[k * 72 + d] / (g_RtE[k * 72 + 64] + EPSV);
        }
        __syncthreads();
        for (int i = t; i < KC * 72; i += 256) g_RtE[i] = 0.f;
        if (t == 0) g_ticket = 0u;
    }
}

// ---------------------------------------------------------------------------
__global__ void finalize_kernel(float* out) {
    out[0] = g_dec * (1.f / (float)NDATA) + ALPHA * (g_loss * (1.f / (float)NROWS));
}

// ---------------------------------------------------------------------------
extern "C" void kernel_launch(void* const* d_in, const int* in_sizes, int n_in,
                              void* d_out, int out_size) {
    const float* X   = (const float*)d_in[0];
    const float* enc = (const float*)d_in[1];
    const float* dec = (const float*)d_in[2];
    if (n_in >= 3) {
        if (in_sizes[0] == NROWS * DLAT)      { enc = (const float*)d_in[0]; X = (const float*)d_in[1]; dec = (const float*)d_in[2]; }
        else if (in_sizes[2] == NROWS * DLAT) { enc = (const float*)d_in[2]; dec = (const float*)d_in[1]; }
    }
    float* out = (float*)d_out;

    const int SMEM_F = KC * SC_ST + KC + 256 + 256 * SE_ST + KC * SRT_ST;
    const int SMEM_BYTES = SMEM_F * 4;   // 163072
    cudaFuncSetAttribute(iter_kernel, cudaFuncAttributeMaxDynamicSharedMemorySize, SMEM_BYTES);

    init_kernel<<<1, 256>>>(enc);
    decoder_kernel<<<2048, 256>>>((const float4*)X, (const float4*)dec, NDATA / 4);
    for (int it = 0; it < 10; it++)
        iter_kernel<<<128, 256, SMEM_BYTES>>>(enc, it == 9 ? 1 : 0);
    finalize_kernel<<<1, 1>>>(out);
}

// round 7
// speedup vs baseline: 1.8807x; 1.0198x over previous
#include <cuda_runtime.h>
#include <cuda_bf16.h>
#include <cstdint>

// ---------------------------------------------------------------------------
// ClusterLoss via tf32 mma.sync, 512-thread CTAs (16 warps) for latency hiding.
// out = mean((X-dec)^2) + ALPHA * soft_kmeans_loss(enc, K=64), 10 iters.
// ---------------------------------------------------------------------------

#define NROWS   65536
#define DLAT    64
#define KC      64
#define NDATA   33554432
#define ALPHA   0.001f
#define EPSV    1e-8f

#define SE_ST   76      // sE row stride (u32): cols 0..63 data, 64 = ones, 65.. pad
#define SC_ST   68
#define SRT_ST  260     // sRT: [cluster][row] transposed R, 64 x 256

__device__ float    g_C[KC * DLAT];
__device__ float    g_RtE[KC * 72];      // col 64 = sumR
__device__ float    g_dec;
__device__ float    g_loss;
__device__ unsigned g_ticket;

// ---------------------------------------------------------------------------
__global__ void init_kernel(const float* __restrict__ enc) {
    int t = threadIdx.x;
    for (int i = t; i < KC * DLAT; i += blockDim.x) g_C[i] = enc[i];
    for (int i = t; i < KC * 72;   i += blockDim.x) g_RtE[i] = 0.f;
    if (t == 0) { g_dec = 0.f; g_loss = 0.f; g_ticket = 0u; }
}

// ---------------------------------------------------------------------------
__global__ void decoder_kernel(const float4* __restrict__ X,
                               const float4* __restrict__ Dc, int n4) {
    float s = 0.f;
    for (int i = blockIdx.x * blockDim.x + threadIdx.x; i < n4;
         i += gridDim.x * blockDim.x) {
        float4 x = __ldg(X + i);
        float4 d = __ldg(Dc + i);
        float a = x.x - d.x, b = x.y - d.y, c = x.z - d.z, w = x.w - d.w;
        s = fmaf(a, a, fmaf(b, b, fmaf(c, c, fmaf(w, w, s))));
    }
    #pragma unroll
    for (int o = 16; o; o >>= 1) s += __shfl_down_sync(0xffffffffu, s, o);
    __shared__ float ws[8];
    int lane = threadIdx.x & 31, wid = threadIdx.x >> 5;
    if (lane == 0) ws[wid] = s;
    __syncthreads();
    if (wid == 0) {
        s = (lane < 8) ? ws[lane] : 0.f;
        #pragma unroll
        for (int o = 4; o; o >>= 1) s += __shfl_down_sync(0xffffffffu, s, o);
        if (lane == 0) atomicAdd(&g_dec, s);
    }
}

// ---------------------------------------------------------------------------
__device__ __forceinline__ uint32_t f2tf(float f) {
    uint32_t u;
    asm("cvt.rna.tf32.f32 %0, %1;" : "=r"(u) : "f"(f));
    return u;
}

__device__ __forceinline__ void mma_tf32(float& d0, float& d1, float& d2, float& d3,
                                         uint32_t a0, uint32_t a1, uint32_t a2, uint32_t a3,
                                         uint32_t b0, uint32_t b1) {
    asm volatile(
        "mma.sync.aligned.m16n8k8.row.col.f32.tf32.tf32.f32 "
        "{%0,%1,%2,%3}, {%4,%5,%6,%7}, {%8,%9}, {%0,%1,%2,%3};"
        : "+f"(d0), "+f"(d1), "+f"(d2), "+f"(d3)
        : "r"(a0), "r"(a1), "r"(a2), "r"(a3), "r"(b0), "r"(b1));
}

// exp(x), x<=0, FMA-pipe only.
__device__ __forceinline__ float fexp(float x) {
    float y = x * 1.44269504f;
    y = fmaxf(y, -126.0f);
    float t = y + 12582912.0f;
    float n = t - 12582912.0f;
    float f = y - n;
    float p = 0.00961812911f;
    p = fmaf(p, f, 0.0555041087f);
    p = fmaf(p, f, 0.240226507f);
    p = fmaf(p, f, 0.693147181f);
    p = fmaf(p, f, 1.0f);
    float s = __int_as_float((__float_as_int(t) << 23) + 0x3F800000);
    return s * p;
}

// ---------------------------------------------------------------------------
// Grid = 128 CTAs x 2 tiles of 256 rows. 512 threads (16 warps).
// GEMM1: warp w -> 16-row m-tile. GEMM2: warp = (mt2, k-half, n-half).
extern __shared__ float s_dyn[];
__global__ void __launch_bounds__(512, 1)
iter_kernel(const float* __restrict__ enc, int is_loss) {
    float* sC  = s_dyn;                       // 64*68
    float* sC2 = sC + KC * SC_ST;             // 64
    float* sX2 = sC2 + KC;                    // 256
    float* sE  = sX2 + 256;                   // 256*76
    float* sRT = sE + 256 * SE_ST;            // 64*260
    uint32_t* uC  = (uint32_t*)sC;
    uint32_t* uE  = (uint32_t*)sE;
    uint32_t* uRT = (uint32_t*)sRT;
    __shared__ float ws[16];
    __shared__ unsigned s_last;

    int t = threadIdx.x, lane = t & 31, warp = t >> 5;
    int lg = lane >> 2, lt = lane & 3;

    // C -> smem tf32, c2
    for (int i = t; i < KC * DLAT; i += 512) {
        int k = i >> 6, d = i & 63;
        uC[k * SC_ST + d] = f2tf(g_C[i]);
    }
    __syncthreads();
    if (t < KC) {
        float s = 0.f;
        #pragma unroll
        for (int d = 0; d < DLAT; d++) { float c = sC[t * SC_ST + d]; s = fmaf(c, c, s); }
        sC2[t] = s;
    }

    // GEMM2 warp roles
    int mt2    = warp & 3;
    int kh     = (warp >> 2) & 1;
    int nh     = warp >> 3;
    int ntbase = nh ? 5 : 0;
    int ntcnt  = nh ? 4 : 5;
    float acc2[5][4];
    #pragma unroll
    for (int j = 0; j < 5; j++)
        #pragma unroll
        for (int c = 0; c < 4; c++) acc2[j][c] = 0.f;

    float blk_loss = 0.f;
    int m0 = warp * 16;                        // GEMM1 m-tile (16 rows)

    for (int tile = 0; tile < 2; tile++) {
        __syncthreads();                       // protect sE/sRT reuse
        int row0 = (blockIdx.x * 2 + tile) * 256;

        // Load E tile: 2 threads per row, 32 floats each, vectorized stores.
        {
            int row = t >> 1, half = t & 1, cb = half * 32;
            const float4* ep = (const float4*)(enc + (size_t)(row0 + row) * DLAT + cb);
            uint4* dst = (uint4*)(uE + row * SE_ST + cb);
            float x2 = 0.f;
            #pragma unroll
            for (int j = 0; j < 8; j++) {
                float4 v = __ldg(ep + j);
                uint4 u;
                u.x = f2tf(v.x); u.y = f2tf(v.y); u.z = f2tf(v.z); u.w = f2tf(v.w);
                dst[j] = u;
                float f0 = __uint_as_float(u.x), f1 = __uint_as_float(u.y);
                float f2 = __uint_as_float(u.z), f3 = __uint_as_float(u.w);
                x2 = fmaf(f0, f0, fmaf(f1, f1, fmaf(f2, f2, fmaf(f3, f3, x2))));
            }
            x2 += __shfl_xor_sync(0xffffffffu, x2, 1);
            if (half == 0) sX2[row] = x2;
            else {
                uE[row * SE_ST + 64] = f2tf(1.0f);   // ones col -> sumR
                #pragma unroll
                for (int j = 65; j < SE_ST; j++) uE[row * SE_ST + j] = 0u;
            }
        }
        __syncthreads();

        // ---- GEMM1: dots = E_tile @ C^T (m=16/warp, n=64, k=64) ----
        float acc[8][4];
        #pragma unroll
        for (int nt = 0; nt < 8; nt++)
            #pragma unroll
            for (int c = 0; c < 4; c++) acc[nt][c] = 0.f;

        #pragma unroll
        for (int kt = 0; kt < 8; kt++) {
            int k0 = kt * 8;
            int r = m0 + lg;
            uint32_t a0 = uE[r * SE_ST + k0 + lt];
            uint32_t a1 = uE[(r + 8) * SE_ST + k0 + lt];
            uint32_t a2 = uE[r * SE_ST + k0 + lt + 4];
            uint32_t a3 = uE[(r + 8) * SE_ST + k0 + lt + 4];
            #pragma unroll
            for (int nt = 0; nt < 8; nt++) {
                uint32_t b0 = uC[(nt * 8 + lg) * SC_ST + k0 + lt];
                uint32_t b1 = uC[(nt * 8 + lg) * SC_ST + k0 + lt + 4];
                mma_tf32(acc[nt][0], acc[nt][1], acc[nt][2], acc[nt][3],
                         a0, a1, a2, a3, b0, b1);
            }
        }

        // ---- softmax epilogue in fragment layout ----
        #pragma unroll
        for (int h = 0; h < 2; h++) {
            int rloc = m0 + h * 8 + lg;
            float x2v = sX2[rloc];
            float vals[16];
            #pragma unroll
            for (int nt = 0; nt < 8; nt++) {
                #pragma unroll
                for (int c = 0; c < 2; c++) {
                    int col = nt * 8 + lt * 2 + c;
                    float dot = acc[nt][h * 2 + c];
                    vals[nt * 2 + c] = fmaxf(x2v + sC2[col] - 2.f * dot, 0.f);
                }
            }
            float mn = vals[0];
            #pragma unroll
            for (int j = 1; j < 16; j++) mn = fminf(mn, vals[j]);
            mn = fminf(mn, __shfl_xor_sync(0xffffffffu, mn, 1));
            mn = fminf(mn, __shfl_xor_sync(0xffffffffu, mn, 2));
            float se = 0.f, sed = 0.f;
            #pragma unroll
            for (int j = 0; j < 16; j++) {
                float ev = fexp(mn - vals[j]);
                se += ev;
                sed = fmaf(ev, vals[j], sed);
                vals[j] = ev;
            }
            se += __shfl_xor_sync(0xffffffffu, se, 1);
            se += __shfl_xor_sync(0xffffffffu, se, 2);
            if (is_loss) {
                sed += __shfl_xor_sync(0xffffffffu, sed, 1);
                sed += __shfl_xor_sync(0xffffffffu, sed, 2);
                if (lt == 0) blk_loss += sed / se;
            } else {
                float inv = 1.f / se;
                #pragma unroll
                for (int nt = 0; nt < 8; nt++) {
                    #pragma unroll
                    for (int c = 0; c < 2; c++) {
                        int col = nt * 8 + lt * 2 + c;
                        uRT[col * SRT_ST + rloc] = f2tf(vals[nt * 2 + c] * inv);
                    }
                }
            }
        }
        if (is_loss) continue;
        __syncthreads();                       // sRT ready

        // ---- GEMM2: RtE += R^T (64x256) @ [E|1] (256x72), k split in half ----
        #pragma unroll 4
        for (int kt = kh * 16; kt < kh * 16 + 16; kt++) {
            int k0 = kt * 8;
            int ar = mt2 * 16 + lg;
            uint32_t a0 = uRT[ar * SRT_ST + k0 + lt];
            uint32_t a1 = uRT[(ar + 8) * SRT_ST + k0 + lt];
            uint32_t a2 = uRT[ar * SRT_ST + k0 + lt + 4];
            uint32_t a3 = uRT[(ar + 8) * SRT_ST + k0 + lt + 4];
            #pragma unroll
            for (int j = 0; j < 5; j++) {
                if (j < ntcnt) {
                    int n0 = (ntbase + j) * 8;
                    uint32_t b0 = uE[(k0 + lt) * SE_ST + n0 + lg];
                    uint32_t b1 = uE[(k0 + lt + 4) * SE_ST + n0 + lg];
                    mma_tf32(acc2[j][0], acc2[j][1], acc2[j][2], acc2[j][3],
                             a0, a1, a2, a3, b0, b1);
                }
            }
        }
    }

    if (is_loss) {
        #pragma unroll
        for (int o = 16; o; o >>= 1) blk_loss += __shfl_down_sync(0xffffffffu, blk_loss, o);
        if (lane == 0) ws[warp] = blk_loss;
        __syncthreads();
        if (warp == 0) {
            blk_loss = (lane < 16) ? ws[lane] : 0.f;
            #pragma unroll
            for (int o = 8; o; o >>= 1) blk_loss += __shfl_down_sync(0xffffffffu, blk_loss, o);
            if (lane == 0) atomicAdd(&g_loss, blk_loss);
        }
        return;
    }

    // Reduce GEMM2 partials into g_RtE (both k-halves add atomically).
    #pragma unroll
    for (int j = 0; j < 5; j++) {
        if (j < ntcnt) {
            int n0 = (ntbase + j) * 8;
            int m  = mt2 * 16 + lg;
            int c0 = n0 + lt * 2;
            atomicAdd(&g_RtE[m * 72 + c0],           acc2[j][0]);
            atomicAdd(&g_RtE[m * 72 + c0 + 1],       acc2[j][1]);
            atomicAdd(&g_RtE[(m + 8) * 72 + c0],     acc2[j][2]);
            atomicAdd(&g_RtE[(m + 8) * 72 + c0 + 1], acc2[j][3]);
        }
    }

    // Last block updates C.
    __threadfence();
    __syncthreads();
    if (t == 0)
        s_last = (atomicAdd(&g_ticket, 1u) == (unsigned)(gridDim.x - 1)) ? 1u : 0u;
    __syncthreads();
    if (s_last) {
        __threadfence();
        for (int i = t; i < KC * DLAT; i += 512) {
            int k = i >> 6, d = i & 63;
            g_C[i] = g_RtE[k * 72 + d] / (g_RtE[k * 72 + 64] + EPSV);
        }
        __syncthreads();
        for (int i = t; i < KC * 72; i += 512) g_RtE[i] = 0.f;
        if (t == 0) g_ticket = 0u;
    }
}

// ---------------------------------------------------------------------------
__global__ void finalize_kernel(float* out) {
    out[0] = g_dec * (1.f / (float)NDATA) + ALPHA * (g_loss * (1.f / (float)NROWS));
}

// ---------------------------------------------------------------------------
extern "C" void kernel_launch(void* const* d_in, const int* in_sizes, int n_in,
                              void* d_out, int out_size) {
    const float* X   = (const float*)d_in[0];
    const float* enc = (const float*)d_in[1];
    const float* dec = (const float*)d_in[2];
    if (n_in >= 3) {
        if (in_sizes[0] == NROWS * DLAT)      { enc = (const float*)d_in[0]; X = (const float*)d_in[1]; dec = (const float*)d_in[2]; }
        else if (in_sizes[2] == NROWS * DLAT) { enc = (const float*)d_in[2]; dec = (const float*)d_in[1]; }
    }
    float* out = (float*)d_out;

    const int SMEM_F = KC * SC_ST + KC + 256 + 256 * SE_ST + KC * SRT_ST;
    const int SMEM_BYTES = SMEM_F * 4;   // 163072
    cudaFuncSetAttribute(iter_kernel, cudaFuncAttributeMaxDynamicSharedMemorySize, SMEM_BYTES);

    init_kernel<<<1, 256>>>(enc);
    decoder_kernel<<<2048, 256>>>((const float4*)X, (const float4*)dec, NDATA / 4);
    for (int it = 0; it < 10; it++)
        iter_kernel<<<128, 512, SMEM_BYTES>>>(enc, it == 9 ? 1 : 0);
    finalize_kernel<<<1, 1>>>(out);
}